// round 15
// baseline (speedup 1.0000x reference)
#include <cuda_runtime.h>

// MatchNet: per-row MLP(6->20->20->20->8, tanh) + 150-iter PDHG LP.
// R15 = R14 + full f32x2 packing of lane-parallel PDHG work (fma-pipe ops
// 88 -> 63/iter). Cross-lane gathers/gy and fmax stay scalar (fmax -> alu).
// Kernel is pipe-bound (96% of 352-cyc fma demand); f32x2 retires 2 lanes
// per fma-pipe issue. Per-lane arithmetic bit-identical; norm association
// changes to even/odd lanes (validated reassociation class).

#define NTHREADS 256
#define PDHG_ITERS 150

#define TAU  0.18898223650461357f   /* 1/sqrt(28) */
#define SGM  0.18898223650461357f   /* sigma = tau */
#define TCC  1.8898223650461357f    /* tau * control_strength(10) */

typedef unsigned long long u64;

__device__ __forceinline__ u64 pk(float a, float b) {
    u64 r; asm("mov.b64 %0, {%1, %2};" : "=l"(r) : "f"(a), "f"(b)); return r;
}
__device__ __forceinline__ void upk(float& a, float& b, u64 p) {
    asm("mov.b64 {%0, %1}, %2;" : "=f"(a), "=f"(b) : "l"(p));
}
__device__ __forceinline__ u64 fma2(u64 a, u64 b, u64 c) {
    u64 d; asm("fma.rn.f32x2 %0, %1, %2, %3;" : "=l"(d) : "l"(a), "l"(b), "l"(c)); return d;
}
__device__ __forceinline__ u64 mul2(u64 a, u64 b) {
    u64 d; asm("mul.rn.f32x2 %0, %1, %2;" : "=l"(d) : "l"(a), "l"(b)); return d;
}
__device__ __forceinline__ float fast_rsqrt(float v) {
    float r; asm("rsqrt.approx.f32 %0, %1;" : "=f"(r) : "f"(v)); return r;
}
__device__ __forceinline__ float fast_tanh(float x) {
    float e = __expf(2.0f * x);
    return 1.0f - __fdividef(2.0f, e + 1.0f);
}
// a + b / a - b as FFMA-imm (exact; keeps R14 forms)
__device__ __forceinline__ float fai(float a, float b) {
    float r;
    asm("fma.rn.f32 %0, %1, 0f3F800000, %2;" : "=f"(r) : "f"(a), "f"(b));
    return r;
}
__device__ __forceinline__ float fsi(float a, float b) {
    float r;
    asm("fma.rn.f32 %0, %1, 0fBF800000, %2;" : "=f"(r) : "f"(b), "f"(a));
    return r;
}

__global__ __launch_bounds__(NTHREADS)
void matchnet_kernel(
    const float* __restrict__ X,
    const float* __restrict__ W1, const float* __restrict__ b1,
    const float* __restrict__ W2, const float* __restrict__ b2,
    const float* __restrict__ W3, const float* __restrict__ b3,
    const float* __restrict__ W4, const float* __restrict__ b4,
    float* __restrict__ out, int B)
{
    __shared__ __align__(16) float sW1[120], sW2[400], sW3[400], sW4[160];
    __shared__ __align__(16) float sb1[20], sb2[20], sb3[20], sb4[8];

    const int t = threadIdx.x;
    for (int i = t; i < 120; i += NTHREADS) sW1[i] = W1[i];
    for (int i = t; i < 400; i += NTHREADS) sW2[i] = W2[i];
    for (int i = t; i < 400; i += NTHREADS) sW3[i] = W3[i];
    for (int i = t; i < 160; i += NTHREADS) sW4[i] = W4[i];
    if (t < 20) { sb1[t] = b1[t]; sb2[t] = b2[t]; sb3[t] = b3[t]; }
    if (t < 8)  { sb4[t] = b4[t]; }
    __syncthreads();

    const int row = blockIdx.x * NTHREADS + t;
    if (row >= B) return;

    // ---- input row (RHS b of the LP) ----
    float Z0, Z1, Z2, Z3, Z4, Z5;
    {
        const float2* p = (const float2*)(X + row * 6);
        float2 a0 = p[0], a1 = p[1], a2 = p[2];
        Z0 = a0.x; Z1 = a0.y; Z2 = a1.x;
        Z3 = a1.y; Z4 = a2.x; Z5 = a2.y;
    }

    // ---- MLP, f32x2-packed (validated R6-R14) ----
    float h[20], h2[20];
    {
        float Zv[6] = {Z0, Z1, Z2, Z3, Z4, Z5};
        u64 a[10];
#pragma unroll
        for (int jp = 0; jp < 10; jp++) a[jp] = *(const u64*)&sb1[2 * jp];
#pragma unroll
        for (int k = 0; k < 6; k++) {
            u64 zz = pk(Zv[k], Zv[k]);
#pragma unroll
            for (int jp = 0; jp < 10; jp++)
                a[jp] = fma2(zz, *(const u64*)&sW1[k * 20 + 2 * jp], a[jp]);
        }
#pragma unroll
        for (int jp = 0; jp < 10; jp++) {
            float s0, s1; upk(s0, s1, a[jp]);
            h[2 * jp] = fast_tanh(s0); h[2 * jp + 1] = fast_tanh(s1);
        }
    }
    {
        u64 a[10];
#pragma unroll
        for (int jp = 0; jp < 10; jp++) a[jp] = *(const u64*)&sb2[2 * jp];
#pragma unroll
        for (int k = 0; k < 20; k++) {
            u64 hh = pk(h[k], h[k]);
#pragma unroll
            for (int jp = 0; jp < 10; jp++)
                a[jp] = fma2(hh, *(const u64*)&sW2[k * 20 + 2 * jp], a[jp]);
        }
#pragma unroll
        for (int jp = 0; jp < 10; jp++) {
            float s0, s1; upk(s0, s1, a[jp]);
            h2[2 * jp] = fast_tanh(s0); h2[2 * jp + 1] = fast_tanh(s1);
        }
    }
    {
        u64 a[10];
#pragma unroll
        for (int jp = 0; jp < 10; jp++) a[jp] = *(const u64*)&sb3[2 * jp];
#pragma unroll
        for (int k = 0; k < 20; k++) {
            u64 hh = pk(h2[k], h2[k]);
#pragma unroll
            for (int jp = 0; jp < 10; jp++)
                a[jp] = fma2(hh, *(const u64*)&sW3[k * 20 + 2 * jp], a[jp]);
        }
#pragma unroll
        for (int jp = 0; jp < 10; jp++) {
            float s0, s1; upk(s0, s1, a[jp]);
            h[2 * jp] = fast_tanh(s0); h[2 * jp + 1] = fast_tanh(s1);
        }
    }
    float z[8];
    {
        u64 a[4];
#pragma unroll
        for (int jp = 0; jp < 4; jp++) a[jp] = *(const u64*)&sb4[2 * jp];
#pragma unroll
        for (int k = 0; k < 20; k++) {
            u64 hh = pk(h[k], h[k]);
#pragma unroll
            for (int jp = 0; jp < 4; jp++)
                a[jp] = fma2(hh, *(const u64*)&sW4[k * 8 + 2 * jp], a[jp]);
        }
#pragma unroll
        for (int jp = 0; jp < 4; jp++) upk(z[2 * jp], z[2 * jp + 1], a[jp]);
    }

    // ---- anti-phase stagger: warps 4-7 delay ~144 cyc ----
    if ((t >> 5) >= 4) {
        float acc = 1.0f;
#pragma unroll 1
        for (int i = 0; i < 36; i++)
            asm volatile("fma.rn.f32 %0, %0, 0f3F7FFF58, 0f38D1B717;" : "+f"(acc));
    }

    // ---- packed constants (live in registers across the loop) ----
    const u64 SGM2  = pk(SGM, SGM);
    const u64 NSGM2 = pk(-SGM, -SGM);
    const u64 NTAU2 = pk(-TAU, -TAU);
    const u64 TWO2  = pk(2.0f, 2.0f);
    const u64 NONE2 = pk(-1.0f, -1.0f);
    const u64 Zp0 = pk(z[0], z[1]), Zp1 = pk(z[2], z[3]);
    const u64 Zp2 = pk(z[4], z[5]), Zp3 = pk(z[6], z[7]);

    // ---- PDHG state init ----
    u64 XB0, XB1, XB2v, XB3, SDN0, SDN1, SDN2v, SDN3, ZM0, ZM1, ZM2v, ZM3;
    {
        float x00 = fmaxf(z[0], 0.0f), x01 = fmaxf(z[1], 0.0f);
        float x02 = fmaxf(z[2], 0.0f), x03 = fmaxf(z[3], 0.0f);
        float x04 = fmaxf(z[4], 0.0f), x05 = fmaxf(z[5], 0.0f);
        float x06 = fmaxf(z[6], 0.0f), x07 = fmaxf(z[7], 0.0f);
        float sd0 = x00 - z[0], sd1 = x01 - z[1], sd2 = x02 - z[2], sd3 = x03 - z[3];
        float sd4 = x04 - z[4], sd5 = x05 - z[5], sd6 = x06 - z[6], sd7 = x07 - z[7];
        XB0 = pk(x00, x01); XB1 = pk(x02, x03); XB2v = pk(x04, x05); XB3 = pk(x06, x07);
        SDN0 = pk(sd0, sd1); SDN1 = pk(sd2, sd3); SDN2v = pk(sd4, sd5); SDN3 = pk(sd6, sd7);
        ZM0 = pk(z[0] - sd0, z[1] - sd1); ZM1 = pk(z[2] - sd2, z[3] - sd3);
        ZM2v = pk(z[4] - sd4, z[5] - sd5); ZM3 = pk(z[6] - sd6, z[7] - sd7);
    }
    float y0 = 0.f, y1 = 0.f, y2 = 0.f, y3 = 0.f, y4 = 0.f, y5 = 0.f;
    float w0 = 1.f, w1 = 1.f, w2 = 1.f, w3 = 1.f,
          w4 = 1.f, w5 = 1.f, w6 = 1.f, w7 = 1.f;

#pragma unroll 2
    for (int it = 0; it < PDHG_ITERS; it++) {
        // ---- unpack xb for cross-lane work ----
        float xb0, xb1, xb2, xb3, xb4, xb5, xb6, xb7;
        upk(xb0, xb1, XB0); upk(xb2, xb3, XB1);
        upk(xb4, xb5, XB2v); upk(xb6, xb7, XB3);

        // ---- s = S*xb - Z via shared pairs (scalar, 17 ops) ----
        float A  = fai(xb2, xb5);
        float Bp = fai(xb1, xb4);
        float C  = fai(xb0, xb6);
        float s0 = fai(fsi(fai(xb0, xb7), Z0), A);
        float s1 = fai(Bp, fsi(xb3, Z1));
        float s2 = fai(C, fsi(xb1, Z2));
        float s3 = fai(A, fsi(xb3, Z3));
        float s4 = fai(fsi(Bp, Z4), fai(xb2, xb7));
        float s5 = fai(C, fsi(xb4, Z5));

        // ---- y update: packed fma, scalar fmax (alu) ----
        {
            u64 ty0 = fma2(SGM2, pk(s0, s1), pk(y0, y1));
            u64 ty1 = fma2(SGM2, pk(s2, s3), pk(y2, y3));
            u64 ty2 = fma2(SGM2, pk(s4, s5), pk(y4, y5));
            float a, b;
            upk(a, b, ty0); y0 = fmaxf(0.0f, a); y1 = fmaxf(0.0f, b);
            upk(a, b, ty1); y2 = fmaxf(0.0f, a); y3 = fmaxf(0.0f, b);
            upk(a, b, ty2); y4 = fmaxf(0.0f, a); y5 = fmaxf(0.0f, b);
        }
        // ---- w update: packed fma (uses packed XB), scalar fmax ----
        {
            u64 tw0 = fma2(NSGM2, XB0,  pk(w0, w1));
            u64 tw1 = fma2(NSGM2, XB1,  pk(w2, w3));
            u64 tw2 = fma2(NSGM2, XB2v, pk(w4, w5));
            u64 tw3 = fma2(NSGM2, XB3,  pk(w6, w7));
            float a, b;
            upk(a, b, tw0); w0 = fmaxf(1.0f, a); w1 = fmaxf(1.0f, b);
            upk(a, b, tw1); w2 = fmaxf(1.0f, a); w3 = fmaxf(1.0f, b);
            upk(a, b, tw2); w4 = fmaxf(1.0f, a); w5 = fmaxf(1.0f, b);
            upk(a, b, tw3); w6 = fmaxf(1.0f, a); w7 = fmaxf(1.0f, b);
        }

        // ---- gy = S^T y - YIp (scalar, 17 ops) ----
        float q25 = fai(y2, y5), q04 = fai(y0, y4), q14 = fai(y1, y4);
        float gy0 = fsi(fai(y0, q25), w0);
        float gy1 = fsi(fai(q14, y2), w1);
        float gy2 = fsi(fai(q04, y3), w2);
        float gy3 = fsi(fai(y1, y3), w3);
        float gy4 = fsi(fai(q14, y5), w4);
        float gy5 = fsi(fai(y0, y3), w5);
        float gy6 = fsi(q25, w6);
        float gy7 = fsi(q04, w7);

        // ---- d = sdn - tau*gy (packed) ----
        u64 D0 = fma2(NTAU2, pk(gy0, gy1), SDN0);
        u64 D1 = fma2(NTAU2, pk(gy2, gy3), SDN1);
        u64 D2 = fma2(NTAU2, pk(gy4, gy5), SDN2v);
        u64 D3 = fma2(NTAU2, pk(gy6, gy7), SDN3);

        // ---- ||d||^2 packed chain (even/odd lanes) + merge ----
        u64 Q = mul2(D0, D0);
        Q = fma2(D1, D1, Q);
        Q = fma2(D2, D2, Q);
        Q = fma2(D3, D3, Q);
        float qa, qb; upk(qa, qb, Q);
        float nn = fai(qa, qb);
        float rr = fast_rsqrt(nn);   // nn=0 -> rr=inf -> scale=0 (exact)
        float scale = fmaxf(0.0f, fmaf(-TCC, rr, 1.0f));
        u64 SC2 = pk(scale, scale);

        // ---- primal (packed): ns = scale*d; xb = 2*ns + zm; zm = z - ns ----
        u64 NS0 = mul2(SC2, D0), NS1 = mul2(SC2, D1);
        u64 NS2 = mul2(SC2, D2), NS3 = mul2(SC2, D3);
        XB0 = fma2(TWO2, NS0, ZM0);
        XB1 = fma2(TWO2, NS1, ZM1);
        XB2v = fma2(TWO2, NS2, ZM2v);
        XB3 = fma2(TWO2, NS3, ZM3);
        ZM0 = fma2(NONE2, NS0, Zp0);   // z - ns (exact)
        ZM1 = fma2(NONE2, NS1, Zp1);
        ZM2v = fma2(NONE2, NS2, Zp2);
        ZM3 = fma2(NONE2, NS3, Zp3);
        SDN0 = NS0; SDN1 = NS1; SDN2v = NS2; SDN3 = NS3;
    }

    // ---- x = z + sdn ----
    float sd0, sd1, sd2, sd3, sd4, sd5, sd6, sd7;
    upk(sd0, sd1, SDN0); upk(sd2, sd3, SDN1);
    upk(sd4, sd5, SDN2v); upk(sd6, sd7, SDN3);
    float4* p = (float4*)(out + row * 8);
    p[0] = make_float4(z[0] + sd0, z[1] + sd1, z[2] + sd2, z[3] + sd3);
    p[1] = make_float4(z[4] + sd4, z[5] + sd5, z[6] + sd6, z[7] + sd7);
}

extern "C" void kernel_launch(void* const* d_in, const int* in_sizes, int n_in,
                              void* d_out, int out_size) {
    const float* X  = (const float*)d_in[0];
    const float* W1 = (const float*)d_in[1];
    const float* b1 = (const float*)d_in[2];
    const float* W2 = (const float*)d_in[3];
    const float* b2 = (const float*)d_in[4];
    const float* W3 = (const float*)d_in[5];
    const float* b3 = (const float*)d_in[6];
    const float* W4 = (const float*)d_in[7];
    const float* b4 = (const float*)d_in[8];

    const int B = in_sizes[0] / 6;
    const int grid = (B + NTHREADS - 1) / NTHREADS;
    matchnet_kernel<<<grid, NTHREADS>>>(X, W1, b1, W2, b2, W3, b3, W4, b4,
                                        (float*)d_out, B);
}

// round 16
// speedup vs baseline: 1.0311x; 1.0311x over previous
#include <cuda_runtime.h>

// MatchNet: per-row MLP(6->20->20->20->8, tanh) + 150-iter PDHG LP.
// R16 = R14 (best, 29.15us) with the anti-phase stagger retuned to the
// measured iteration period: T_iter ~365 cyc -> half-period delay ~184 cyc
// (46 chained FMAs @ lat 4). Body unchanged: kernel sits at >=96% of the
// fma-pipe rt-2 occupancy bound (2 warps x ~90 ops x rt2 = 360 cyc/iter);
// R15 proved f32x2 packing moves zero pipe-cycles (FFMA2 = 2 pipe-cyc).

#define NTHREADS 256
#define PDHG_ITERS 150

#define TAU  0.18898223650461357f   /* 1/sqrt(28) */
#define SGM  0.18898223650461357f   /* sigma = tau */
#define TCC  1.8898223650461357f    /* tau * control_strength(10) */

typedef unsigned long long u64;

__device__ __forceinline__ u64 pk(float a, float b) {
    u64 r; asm("mov.b64 %0, {%1, %2};" : "=l"(r) : "f"(a), "f"(b)); return r;
}
__device__ __forceinline__ void upk(float& a, float& b, u64 p) {
    asm("mov.b64 {%0, %1}, %2;" : "=f"(a), "=f"(b) : "l"(p));
}
__device__ __forceinline__ u64 fma2(u64 a, u64 b, u64 c) {
    u64 d; asm("fma.rn.f32x2 %0, %1, %2, %3;" : "=l"(d) : "l"(a), "l"(b), "l"(c)); return d;
}
__device__ __forceinline__ float fast_rsqrt(float v) {
    float r; asm("rsqrt.approx.f32 %0, %1;" : "=f"(r) : "f"(v)); return r;
}
__device__ __forceinline__ float fast_tanh(float x) {
    float e = __expf(2.0f * x);
    return 1.0f - __fdividef(2.0f, e + 1.0f);
}
// a + b as FFMA-imm (a*1.0 + b): exact.
__device__ __forceinline__ float fai(float a, float b) {
    float r;
    asm("fma.rn.f32 %0, %1, 0f3F800000, %2;" : "=f"(r) : "f"(a), "f"(b));
    return r;
}
// a - b as FFMA-imm (b*(-1.0) + a): exact.
__device__ __forceinline__ float fsi(float a, float b) {
    float r;
    asm("fma.rn.f32 %0, %1, 0fBF800000, %2;" : "=f"(r) : "f"(b), "f"(a));
    return r;
}

__global__ __launch_bounds__(NTHREADS)
void matchnet_kernel(
    const float* __restrict__ X,
    const float* __restrict__ W1, const float* __restrict__ b1,
    const float* __restrict__ W2, const float* __restrict__ b2,
    const float* __restrict__ W3, const float* __restrict__ b3,
    const float* __restrict__ W4, const float* __restrict__ b4,
    float* __restrict__ out, int B)
{
    __shared__ __align__(16) float sW1[120], sW2[400], sW3[400], sW4[160];
    __shared__ __align__(16) float sb1[20], sb2[20], sb3[20], sb4[8];

    const int t = threadIdx.x;
    for (int i = t; i < 120; i += NTHREADS) sW1[i] = W1[i];
    for (int i = t; i < 400; i += NTHREADS) sW2[i] = W2[i];
    for (int i = t; i < 400; i += NTHREADS) sW3[i] = W3[i];
    for (int i = t; i < 160; i += NTHREADS) sW4[i] = W4[i];
    if (t < 20) { sb1[t] = b1[t]; sb2[t] = b2[t]; sb3[t] = b3[t]; }
    if (t < 8)  { sb4[t] = b4[t]; }
    __syncthreads();

    const int row = blockIdx.x * NTHREADS + t;
    if (row >= B) return;

    // ---- input row (RHS b of the LP) ----
    float Z0, Z1, Z2, Z3, Z4, Z5;
    {
        const float2* p = (const float2*)(X + row * 6);
        float2 a0 = p[0], a1 = p[1], a2 = p[2];
        Z0 = a0.x; Z1 = a0.y; Z2 = a1.x;
        Z3 = a1.y; Z4 = a2.x; Z5 = a2.y;
    }

    // ---- MLP, f32x2-packed (validated R6-R15) ----
    float h[20], h2[20];
    {
        float Zv[6] = {Z0, Z1, Z2, Z3, Z4, Z5};
        u64 a[10];
#pragma unroll
        for (int jp = 0; jp < 10; jp++) a[jp] = *(const u64*)&sb1[2 * jp];
#pragma unroll
        for (int k = 0; k < 6; k++) {
            u64 zz = pk(Zv[k], Zv[k]);
#pragma unroll
            for (int jp = 0; jp < 10; jp++)
                a[jp] = fma2(zz, *(const u64*)&sW1[k * 20 + 2 * jp], a[jp]);
        }
#pragma unroll
        for (int jp = 0; jp < 10; jp++) {
            float s0, s1; upk(s0, s1, a[jp]);
            h[2 * jp] = fast_tanh(s0); h[2 * jp + 1] = fast_tanh(s1);
        }
    }
    {
        u64 a[10];
#pragma unroll
        for (int jp = 0; jp < 10; jp++) a[jp] = *(const u64*)&sb2[2 * jp];
#pragma unroll
        for (int k = 0; k < 20; k++) {
            u64 hh = pk(h[k], h[k]);
#pragma unroll
            for (int jp = 0; jp < 10; jp++)
                a[jp] = fma2(hh, *(const u64*)&sW2[k * 20 + 2 * jp], a[jp]);
        }
#pragma unroll
        for (int jp = 0; jp < 10; jp++) {
            float s0, s1; upk(s0, s1, a[jp]);
            h2[2 * jp] = fast_tanh(s0); h2[2 * jp + 1] = fast_tanh(s1);
        }
    }
    {
        u64 a[10];
#pragma unroll
        for (int jp = 0; jp < 10; jp++) a[jp] = *(const u64*)&sb3[2 * jp];
#pragma unroll
        for (int k = 0; k < 20; k++) {
            u64 hh = pk(h2[k], h2[k]);
#pragma unroll
            for (int jp = 0; jp < 10; jp++)
                a[jp] = fma2(hh, *(const u64*)&sW3[k * 20 + 2 * jp], a[jp]);
        }
#pragma unroll
        for (int jp = 0; jp < 10; jp++) {
            float s0, s1; upk(s0, s1, a[jp]);
            h[2 * jp] = fast_tanh(s0); h[2 * jp + 1] = fast_tanh(s1);
        }
    }
    float z[8];
    {
        u64 a[4];
#pragma unroll
        for (int jp = 0; jp < 4; jp++) a[jp] = *(const u64*)&sb4[2 * jp];
#pragma unroll
        for (int k = 0; k < 20; k++) {
            u64 hh = pk(h[k], h[k]);
#pragma unroll
            for (int jp = 0; jp < 4; jp++)
                a[jp] = fma2(hh, *(const u64*)&sW4[k * 8 + 2 * jp], a[jp]);
        }
#pragma unroll
        for (int jp = 0; jp < 4; jp++) upk(z[2 * jp], z[2 * jp + 1], a[jp]);
    }

    // ---- anti-phase stagger: warps 4-7 delay ~184 cyc (half of T_iter~365) ----
    if ((t >> 5) >= 4) {
        float acc = 1.0f;
#pragma unroll 1
        for (int i = 0; i < 46; i++)
            asm volatile("fma.rn.f32 %0, %0, 0f3F7FFF58, 0f38D1B717;" : "+f"(acc));
    }

    // ---- PDHG state init (R11/R13/R14 body) ----
    float sdn0, sdn1, sdn2, sdn3, sdn4, sdn5, sdn6, sdn7;
    float xb0, xb1, xb2, xb3, xb4, xb5, xb6, xb7;
    float zm0, zm1, zm2, zm3, zm4, zm5, zm6, zm7;
    {
        float x00 = fmaxf(z[0], 0.0f), x01 = fmaxf(z[1], 0.0f);
        float x02 = fmaxf(z[2], 0.0f), x03 = fmaxf(z[3], 0.0f);
        float x04 = fmaxf(z[4], 0.0f), x05 = fmaxf(z[5], 0.0f);
        float x06 = fmaxf(z[6], 0.0f), x07 = fmaxf(z[7], 0.0f);
        sdn0 = x00 - z[0]; sdn1 = x01 - z[1]; sdn2 = x02 - z[2]; sdn3 = x03 - z[3];
        sdn4 = x04 - z[4]; sdn5 = x05 - z[5]; sdn6 = x06 - z[6]; sdn7 = x07 - z[7];
        xb0 = x00; xb1 = x01; xb2 = x02; xb3 = x03;
        xb4 = x04; xb5 = x05; xb6 = x06; xb7 = x07;
        zm0 = z[0] - sdn0; zm1 = z[1] - sdn1; zm2 = z[2] - sdn2; zm3 = z[3] - sdn3;
        zm4 = z[4] - sdn4; zm5 = z[5] - sdn5; zm6 = z[6] - sdn6; zm7 = z[7] - sdn7;
    }
    float y0 = 0.f, y1 = 0.f, y2 = 0.f, y3 = 0.f, y4 = 0.f, y5 = 0.f;
    float w0 = 1.f, w1 = 1.f, w2 = 1.f, w3 = 1.f,   // YIp = yI + 1
          w4 = 1.f, w5 = 1.f, w6 = 1.f, w7 = 1.f;

#pragma unroll 2
    for (int it = 0; it < PDHG_ITERS; it++) {
        // ---- s = S*xb - Z via shared pairs (17 imm-FFMA "adds") ----
        float A  = fai(xb2, xb5);
        float Bp = fai(xb1, xb4);
        float C  = fai(xb0, xb6);
        float s0 = fai(fsi(fai(xb0, xb7), Z0), A);   // ((xb0+xb7)-Z0)+A
        float s1 = fai(Bp, fsi(xb3, Z1));            // Bp+(xb3-Z1)
        float s2 = fai(C, fsi(xb1, Z2));             // C+(xb1-Z2)
        float s3 = fai(A, fsi(xb3, Z3));             // A+(xb3-Z3)
        float s4 = fai(fsi(Bp, Z4), fai(xb2, xb7));  // (Bp-Z4)+(xb2+xb7)
        float s5 = fai(C, fsi(xb4, Z5));             // C+(xb4-Z5)

        // ---- dual updates ----
        y0 = fmaxf(0.0f, fmaf(SGM, s0, y0));
        y1 = fmaxf(0.0f, fmaf(SGM, s1, y1));
        y2 = fmaxf(0.0f, fmaf(SGM, s2, y2));
        y3 = fmaxf(0.0f, fmaf(SGM, s3, y3));
        y4 = fmaxf(0.0f, fmaf(SGM, s4, y4));
        y5 = fmaxf(0.0f, fmaf(SGM, s5, y5));

        w0 = fmaxf(1.0f, fmaf(-SGM, xb0, w0));
        w1 = fmaxf(1.0f, fmaf(-SGM, xb1, w1));
        w2 = fmaxf(1.0f, fmaf(-SGM, xb2, w2));
        w3 = fmaxf(1.0f, fmaf(-SGM, xb3, w3));
        w4 = fmaxf(1.0f, fmaf(-SGM, xb4, w4));
        w5 = fmaxf(1.0f, fmaf(-SGM, xb5, w5));
        w6 = fmaxf(1.0f, fmaf(-SGM, xb6, w6));
        w7 = fmaxf(1.0f, fmaf(-SGM, xb7, w7));

        // ---- gy = S^T y - YIp (imm-FFMA adds/subs, q-reuse) ----
        float q25 = fai(y2, y5), q04 = fai(y0, y4), q14 = fai(y1, y4);
        float gy0 = fsi(fai(y0, q25), w0);
        float gy1 = fsi(fai(q14, y2), w1);
        float gy2 = fsi(fai(q04, y3), w2);
        float gy3 = fsi(fai(y1, y3), w3);
        float gy4 = fsi(fai(q14, y5), w4);
        float gy5 = fsi(fai(y0, y3), w5);
        float gy6 = fsi(q25, w6);
        float gy7 = fsi(q04, w7);

        // ---- d = sdn - tau*gy (imm-FFMA) ----
        float d0 = fmaf(-TAU, gy0, sdn0);
        float d1 = fmaf(-TAU, gy1, sdn1);
        float d2 = fmaf(-TAU, gy2, sdn2);
        float d3 = fmaf(-TAU, gy3, sdn3);
        float d4 = fmaf(-TAU, gy4, sdn4);
        float d5 = fmaf(-TAU, gy5, sdn5);
        float d6 = fmaf(-TAU, gy6, sdn6);
        float d7 = fmaf(-TAU, gy7, sdn7);

        // ---- ||d||^2: two 4-chains + imm-add; rsqrt; scale ----
        float na = d0 * d0;
        na = fmaf(d1, d1, na);
        na = fmaf(d2, d2, na);
        na = fmaf(d3, d3, na);
        float nb = d4 * d4;
        nb = fmaf(d5, d5, nb);
        nb = fmaf(d6, d6, nb);
        nb = fmaf(d7, d7, nb);
        float nn = fai(na, nb);
        float rr = fast_rsqrt(nn);   // nn=0 -> rr=inf -> scale=0 (exact)
        float scale = fmaxf(0.0f, fmaf(-TCC, rr, 1.0f));

        // ---- primal: ns = scale*d; xb = 2*ns + zm; zm = z - ns ----
        float ns0 = scale * d0, ns1 = scale * d1, ns2 = scale * d2, ns3 = scale * d3;
        float ns4 = scale * d4, ns5 = scale * d5, ns6 = scale * d6, ns7 = scale * d7;

        xb0 = fmaf(2.0f, ns0, zm0); zm0 = fsi(z[0], ns0); sdn0 = ns0;
        xb1 = fmaf(2.0f, ns1, zm1); zm1 = fsi(z[1], ns1); sdn1 = ns1;
        xb2 = fmaf(2.0f, ns2, zm2); zm2 = fsi(z[2], ns2); sdn2 = ns2;
        xb3 = fmaf(2.0f, ns3, zm3); zm3 = fsi(z[3], ns3); sdn3 = ns3;
        xb4 = fmaf(2.0f, ns4, zm4); zm4 = fsi(z[4], ns4); sdn4 = ns4;
        xb5 = fmaf(2.0f, ns5, zm5); zm5 = fsi(z[5], ns5); sdn5 = ns5;
        xb6 = fmaf(2.0f, ns6, zm6); zm6 = fsi(z[6], ns6); sdn6 = ns6;
        xb7 = fmaf(2.0f, ns7, zm7); zm7 = fsi(z[7], ns7); sdn7 = ns7;
    }

    // ---- x = z + sdn ----
    float4* p = (float4*)(out + row * 8);
    p[0] = make_float4(z[0] + sdn0, z[1] + sdn1, z[2] + sdn2, z[3] + sdn3);
    p[1] = make_float4(z[4] + sdn4, z[5] + sdn5, z[6] + sdn6, z[7] + sdn7);
}

extern "C" void kernel_launch(void* const* d_in, const int* in_sizes, int n_in,
                              void* d_out, int out_size) {
    const float* X  = (const float*)d_in[0];
    const float* W1 = (const float*)d_in[1];
    const float* b1 = (const float*)d_in[2];
    const float* W2 = (const float*)d_in[3];
    const float* b2 = (const float*)d_in[4];
    const float* W3 = (const float*)d_in[5];
    const float* b3 = (const float*)d_in[6];
    const float* W4 = (const float*)d_in[7];
    const float* b4 = (const float*)d_in[8];

    const int B = in_sizes[0] / 6;
    const int grid = (B + NTHREADS - 1) / NTHREADS;
    matchnet_kernel<<<grid, NTHREADS>>>(X, W1, b1, W2, b2, W3, b3, W4, b4,
                                        (float*)d_out, B);
}